// round 13
// baseline (speedup 1.0000x reference)
#include <cuda_runtime.h>
#include <cuda_bf16.h>
#include <cstdint>
#include <math.h>

typedef __nv_bfloat16 bf16;

#define B_ROWS   512
#define T_STEPS  128
#define DIM_IN   256
#define HDIM     1024
#define FOURH    4096

#define BM 64            // rows per rowblk (CTA covers 2 rowblks = 128 rows)
#define BN 32            // columns per gate per block
#define NTH 544          // 16 consumer warps (8 per rowblk) + 1 producer

// Tile images (gmem layout == smem layout):
#define A_TILE_B  10240
#define B_TILE_B  20480
#define A_PLANE_B 5120
#define B_PLANE_B 10240
#define STAGE_B   (2 * A_TILE_B + B_TILE_B)  // 40960 (A0, A1, B)

// smem: [0..16) full mbarriers, [16..32) empty mbarriers, stages at 1024
#define SM_FULL(s)  ((s) * 8)
#define SM_EMPTY(s) (16 + (s) * 8)
#define SM_A0_OFF(s) (1024 + (s) * STAGE_B)
#define SM_A1_OFF(s) (SM_A0_OFF(s) + A_TILE_B)
#define SM_B_OFF(s)  (SM_A0_OFF(s) + 2 * A_TILE_B)
#define SMEM_BYTES  (1024 + 2 * STAGE_B)     // 82944 -> 2 CTAs/SM

// ---------------- persistent device scratch (sorted row space) ----------------
__device__ __align__(128) char g_xt[(size_t)T_STEPS * 8 * 8 * A_TILE_B];
__device__ __align__(128) char g_h1t[2][(size_t)8 * 32 * A_TILE_B];
__device__ __align__(128) char g_h2t[2][(size_t)8 * 32 * A_TILE_B];
__device__ __align__(128) char g_w1t[(size_t)32 * 8  * B_TILE_B];
__device__ __align__(128) char g_u1t[(size_t)32 * 32 * B_TILE_B];
__device__ __align__(128) char g_w2t[(size_t)32 * 32 * B_TILE_B];
__device__ __align__(128) char g_u2t[(size_t)32 * 32 * B_TILE_B];
__device__ float g_c1[(size_t)B_ROWS * HDIM];
__device__ float g_c2[(size_t)B_ROWS * HDIM];
__device__ float g_hfinal[(size_t)B_ROWS * HDIM];
__device__ int   g_perm[B_ROWS];
__device__ int   g_slen[B_ROWS];
__device__ int   g_nact[T_STEPS];

// ---------------- helpers ----------------
__device__ __forceinline__ uint32_t smem_u32(const void* p) {
    uint32_t a;
    asm("{ .reg .u64 t; cvta.to.shared.u64 t, %1; cvt.u32.u64 %0, t; }" : "=r"(a) : "l"(p));
    return a;
}
__device__ __forceinline__ void mbar_init(uint32_t a, uint32_t cnt) {
    asm volatile("mbarrier.init.shared.b64 [%0], %1;" :: "r"(a), "r"(cnt) : "memory");
}
__device__ __forceinline__ void mbar_expect(uint32_t a, uint32_t bytes) {
    asm volatile("mbarrier.arrive.expect_tx.shared.b64 _, [%0], %1;"
                 :: "r"(a), "r"(bytes) : "memory");
}
__device__ __forceinline__ void mbar_arrive(uint32_t a) {
    asm volatile("mbarrier.arrive.shared.b64 _, [%0];" :: "r"(a) : "memory");
}
__device__ __forceinline__ void mbar_wait(uint32_t a, uint32_t parity) {
    asm volatile(
        "{\n\t.reg .pred P;\n\t"
        "WL_%=:\n\t"
        "mbarrier.try_wait.parity.acquire.cta.shared::cta.b64 P, [%0], %1, 0x989680;\n\t"
        "@P bra.uni WD_%=;\n\t"
        "bra.uni WL_%=;\n\t"
        "WD_%=:\n\t}"
        :: "r"(a), "r"(parity) : "memory");
}
__device__ __forceinline__ void bulk_g2s(uint32_t dst, const void* src,
                                         uint32_t bytes, uint32_t mbar) {
    asm volatile(
        "cp.async.bulk.shared::cluster.global.mbarrier::complete_tx::bytes "
        "[%0], [%1], %2, [%3];"
        :: "r"(dst), "l"(src), "r"(bytes), "r"(mbar) : "memory");
}
__device__ __forceinline__ void ldmx4(uint32_t* r, uint32_t a) {
    asm volatile("ldmatrix.sync.aligned.m8n8.x4.shared.b16 {%0,%1,%2,%3}, [%4];"
                 : "=r"(r[0]), "=r"(r[1]), "=r"(r[2]), "=r"(r[3]) : "r"(a));
}
__device__ __forceinline__ void mma_bf16(float* d, const uint32_t* a, const uint32_t* b) {
    asm volatile(
        "mma.sync.aligned.m16n8k16.row.col.f32.bf16.bf16.f32 "
        "{%0,%1,%2,%3}, {%4,%5,%6,%7}, {%8,%9}, {%0,%1,%2,%3};"
        : "+f"(d[0]), "+f"(d[1]), "+f"(d[2]), "+f"(d[3])
        : "r"(a[0]), "r"(a[1]), "r"(a[2]), "r"(a[3]), "r"(b[0]), "r"(b[1]));
}
__device__ __forceinline__ float fsig(float x) { return 1.0f / (1.0f + __expf(-x)); }
__device__ __forceinline__ void split_bf16(float x, bf16& hi, bf16& lo) {
    hi = __float2bfloat16(x);
    lo = __float2bfloat16(x - __bfloat162float(hi));
}

// ---------------- prep kernels ----------------
__global__ void sort_rows(const int* __restrict__ seqlen,
                          int* __restrict__ perm, int* __restrict__ slen,
                          int* __restrict__ nact) {
    __shared__ int keys[B_ROWS];
    const int i = threadIdx.x;
    keys[i] = seqlen[i];
    __syncthreads();
    const int k = keys[i];
    int rank = 0;
    for (int j = 0; j < B_ROWS; ++j) {
        int kj = keys[j];
        rank += (kj > k) || (kj == k && j < i);
    }
    perm[rank] = i;
    slen[rank] = k;
    if (i < T_STEPS) {
        int cnt = 0;
        for (int j = 0; j < B_ROWS; ++j) cnt += (keys[j] >= i + 1);
        nact[i] = cnt;
    }
}

__global__ void split_chars_tiled(const float* __restrict__ x,
                                  const int* __restrict__ perm,
                                  char* __restrict__ xt) {
    const int n = B_ROWS * T_STEPS * DIM_IN;
    int i = blockIdx.x * blockDim.x + threadIdx.x;
    if (i >= n) return;
    const int row_elems = T_STEPS * DIM_IN;
    int bs = i / row_elems, d = i - bs * row_elems;
    int t = d >> 8, k = d & 255;
    float v = x[(size_t)perm[bs] * row_elems + d];
    bf16 h, l; split_bf16(v, h, l);
    size_t base = (((size_t)t * 8 + (bs >> 6)) * 8 + (k >> 5)) * A_TILE_B
                + (size_t)(bs & 63) * 80 + (k & 31) * 2;
    *reinterpret_cast<bf16*>(xt + base)             = h;
    *reinterpret_cast<bf16*>(xt + base + A_PLANE_B) = l;
}

struct TransArgs { const float* W; char* Wt; int K; };
__global__ void transpose_split_w_all(TransArgs t0, TransArgs t1,
                                      TransArgs t2, TransArgs t3) {
    TransArgs ta = (blockIdx.z == 0) ? t0
                 : (blockIdx.z == 1) ? t1
                 : (blockIdx.z == 2) ? t2 : t3;
    int kb = blockIdx.y * 32;
    if (kb >= ta.K) return;
    __shared__ float tile[32][33];
    int nb = blockIdx.x * 32;
    int x = threadIdx.x, y = threadIdx.y;
    #pragma unroll
    for (int yy = y; yy < 32; yy += 8)
        tile[yy][x] = ta.W[(size_t)(kb + yy) * FOURH + nb + x];
    __syncthreads();
    const int KC = ta.K >> 5;
    #pragma unroll
    for (int yy = y; yy < 32; yy += 8) {
        float w = tile[x][yy];
        bf16 h, l; split_bf16(w, h, l);
        int n4 = nb + yy, k = kb + x;
        int g = n4 >> 10, rr = n4 & 1023;
        int nblk = rr >> 5, nl = rr & 31;
        int kc = k >> 5, kl = k & 31;
        size_t base = ((size_t)(nblk * KC + kc)) * B_TILE_B
                    + (size_t)(g * 32 + nl) * 80 + kl * 2;
        *reinterpret_cast<bf16*>(ta.Wt + base)             = h;
        *reinterpret_cast<bf16*>(ta.Wt + base + B_PLANE_B) = l;
    }
}

// ---------------- per-layer step arguments ----------------
struct StepArgs {
    const char* Ax;
    const char* Hx;
    const char* Bw;
    const char* Bu;
    int KC0;
    const float* bias;
    float* C;
    char* Ot;
    const int* seqlen;
    float* hfinal;
    const int* nact;
    int t; int first;
};

// ------- fused dual-layer LSTM step: dual-rowblk B-reuse, warp-specialized -------
__global__ __launch_bounds__(NTH, 2)
void lstm_step(const StepArgs a0, const StepArgs a1)
{
    const StepArgs a = (blockIdx.z == 0) ? a0 : a1;
    const int rbpair = blockIdx.y;              // 0..3
    const int rb0 = rbpair * 2;
    const int row0 = rb0 * BM;                  // first row of pair
    const int nact_t = a.nact[a.t];
    if (row0 >= nact_t) return;
    const int act1 = (row0 + BM < nact_t) ? 1 : 0;   // is second rowblk live?

    extern __shared__ char smemc[];
    const uint32_t sb = smem_u32(smemc);
    const int tid  = threadIdx.x;
    const int lane = tid & 31;
    const int warp = tid >> 5;
    const int nblk = blockIdx.x;
    const int n0   = nblk * BN;

    const int KC0i = a.KC0;
    const int nch = a.first ? KC0i : (KC0i + 32);

    if (tid == 0) {
        #pragma unroll
        for (int s = 0; s < 2; ++s) {
            mbar_init(sb + SM_FULL(s), 1);
            mbar_init(sb + SM_EMPTY(s), 16);
        }
        asm volatile("fence.proxy.async.shared::cta;" ::: "memory");
    }
    __syncthreads();

    if (warp == 16) {
        // ---------------- producer warp ----------------
        if (lane == 0) {
            const uint32_t txb = (uint32_t)(B_TILE_B + A_TILE_B + (act1 ? A_TILE_B : 0));
            for (int c = 0; c < nch; ++c) {
                const int st = c & 1;
                if (c >= 2)
                    mbar_wait(sb + SM_EMPTY(st), (uint32_t)(((c >> 1) - 1) & 1));
                const int seg = (c < KC0i) ? 0 : 1;
                const int kc  = seg ? (c - KC0i) : c;
                const char* A0s = seg ? (a.Hx + ((size_t)(rb0 * 32 + kc)) * A_TILE_B)
                                      : (a.Ax + ((size_t)(rb0 * KC0i + kc)) * A_TILE_B);
                const char* Bs  = seg ? (a.Bu + ((size_t)(nblk * 32 + kc)) * B_TILE_B)
                                      : (a.Bw + ((size_t)(nblk * KC0i + kc)) * B_TILE_B);
                const uint32_t mb = sb + SM_FULL(st);
                mbar_expect(mb, txb);
                bulk_g2s(sb + SM_A0_OFF(st), A0s, A_TILE_B, mb);
                if (act1) {
                    const char* A1s = seg ? (a.Hx + ((size_t)((rb0 + 1) * 32 + kc)) * A_TILE_B)
                                          : (a.Ax + ((size_t)((rb0 + 1) * KC0i + kc)) * A_TILE_B);
                    bulk_g2s(sb + SM_A1_OFF(st), A1s, A_TILE_B, mb);
                }
                bulk_g2s(sb + SM_B_OFF(st), Bs, B_TILE_B, mb);
            }
        }
        return;
    }

    // ---------------- consumer warps (0..15): warp>>3 selects rowblk ----------------
    const int rbl = warp >> 3;           // 0 or 1
    const int w8  = warp & 7;
    const int wm  = w8 >> 1;             // 0..3 -> 16-row slab within rowblk
    const int wn  = w8 & 1;              // 0..1 -> 16-col slab
    const int live = (rbl == 0) || act1;

    const int arow  = (lane & 7) + ((lane >> 3) & 1) * 8;
    const int koffA = (lane >> 4) * 8;
    const int brow4 = (lane & 7) + ((lane >> 4) << 3);
    const int koffB4 = ((lane >> 3) & 1) * 8;

    float acc[4][2][4];
    #pragma unroll
    for (int g = 0; g < 4; ++g)
        #pragma unroll
        for (int nt = 0; nt < 2; ++nt)
            #pragma unroll
            for (int q = 0; q < 4; ++q) acc[g][nt][q] = 0.f;

    const uint32_t aOffBase = (uint32_t)(rbl ? A_TILE_B : 0);

    for (int i = 0; i < nch; ++i) {
        const int st = i & 1;
        mbar_wait(sb + SM_FULL(st), (uint32_t)((i >> 1) & 1));

        if (live) {
            const uint32_t aB = sb + SM_A0_OFF(st) + aOffBase;
            const uint32_t bB = sb + SM_B_OFF(st);
            #pragma unroll
            for (int ks = 0; ks < 2; ++ks) {
                uint32_t ah[4], al[4];
                uint32_t aa = aB + (uint32_t)((wm * 16 + arow) * 80 + (ks * 16 + koffA) * 2);
                ldmx4(ah, aa);
                ldmx4(al, aa + A_PLANE_B);
                #pragma unroll
                for (int g = 0; g < 4; ++g) {
                    uint32_t bh[4], bl[4];
                    uint32_t ba = bB + (uint32_t)((g * 32 + wn * 16 + brow4) * 80
                                                  + (ks * 16 + koffB4) * 2);
                    ldmx4(bh, ba);
                    ldmx4(bl, ba + B_PLANE_B);
                    mma_bf16(acc[g][0], ah, bh);
                    mma_bf16(acc[g][0], ah, bl);
                    mma_bf16(acc[g][0], al, bh);
                    mma_bf16(acc[g][1], ah, bh + 2);
                    mma_bf16(acc[g][1], ah, bl + 2);
                    mma_bf16(acc[g][1], al, bh + 2);
                }
            }
        }
        __syncwarp();
        if (lane == 0) mbar_arrive(sb + SM_EMPTY(st));
    }

    if (!live) return;

    // ---- fused LSTM cell epilogue (h written in tiled A-image layout) ----
    #pragma unroll
    for (int half = 0; half < 2; ++half) {
        const int r = (rb0 + rbl) * BM + wm * 16 + half * 8 + (lane >> 2);
        const int slen = a.seqlen ? a.seqlen[r] : 0;
        #pragma unroll
        for (int nt = 0; nt < 2; ++nt) {
            const int c = n0 + wn * 16 + nt * 8 + (lane & 3) * 2;
            float2 cold = make_float2(0.f, 0.f);
            if (!a.first)
                cold = *reinterpret_cast<const float2*>(a.C + (size_t)r * HDIM + c);
            float cn[2], hn[2];
            #pragma unroll
            for (int j = 0; j < 2; ++j) {
                const int q = half * 2 + j;
                float zi = acc[0][nt][q] + a.bias[c + j];
                float zf = acc[1][nt][q] + a.bias[HDIM + c + j];
                float zg = acc[2][nt][q] + a.bias[2 * HDIM + c + j];
                float zo = acc[3][nt][q] + a.bias[3 * HDIM + c + j];
                float ig = fsig(zi), fg = fsig(zf);
                float gg = tanhf(zg), og = fsig(zo);
                float co = (j == 0) ? cold.x : cold.y;
                cn[j] = fmaf(fg, co, ig * gg);
                hn[j] = og * tanhf(cn[j]);
            }
            *reinterpret_cast<float2*>(a.C + (size_t)r * HDIM + c) = make_float2(cn[0], cn[1]);
            bf16 h0, l0, h1, l1;
            split_bf16(hn[0], h0, l0);
            split_bf16(hn[1], h1, l1);
            size_t toff = ((size_t)((r >> 6) * 32 + (c >> 5))) * A_TILE_B
                        + (size_t)(r & 63) * 80 + (c & 31) * 2;
            *reinterpret_cast<__nv_bfloat162*>(a.Ot + toff) = __nv_bfloat162(h0, h1);
            *reinterpret_cast<__nv_bfloat162*>(a.Ot + toff + A_PLANE_B) =
                __nv_bfloat162(l0, l1);
            if (a.hfinal && slen - 1 == a.t)
                *reinterpret_cast<float2*>(a.hfinal + (size_t)r * HDIM + c) =
                    make_float2(hn[0], hn[1]);
        }
    }
}

// ---------------- final dense(1024->3) + relu (sorted -> original order) ----------------
__global__ void dense_kernel(const float* __restrict__ hfinal,
                             const int* __restrict__ perm,
                             const float* __restrict__ Wd,
                             const float* __restrict__ bd,
                             float* __restrict__ out)
{
    const int bs = blockIdx.x;
    const float* h = hfinal + (size_t)bs * HDIM;

    float s0 = 0.f, s1 = 0.f, s2 = 0.f;
    for (int k = threadIdx.x; k < HDIM; k += blockDim.x) {
        float hv = h[k];
        s0 = fmaf(hv, Wd[k * 3 + 0], s0);
        s1 = fmaf(hv, Wd[k * 3 + 1], s1);
        s2 = fmaf(hv, Wd[k * 3 + 2], s2);
    }
    #pragma unroll
    for (int o = 16; o > 0; o >>= 1) {
        s0 += __shfl_down_sync(0xffffffffu, s0, o);
        s1 += __shfl_down_sync(0xffffffffu, s1, o);
        s2 += __shfl_down_sync(0xffffffffu, s2, o);
    }
    __shared__ float red[8][3];
    const int wid = threadIdx.x >> 5, lane = threadIdx.x & 31;
    if (lane == 0) { red[wid][0] = s0; red[wid][1] = s1; red[wid][2] = s2; }
    __syncthreads();
    if (threadIdx.x == 0) {
        float r0 = 0.f, r1 = 0.f, r2 = 0.f;
        const int nw = blockDim.x >> 5;
        for (int w = 0; w < nw; ++w) { r0 += red[w][0]; r1 += red[w][1]; r2 += red[w][2]; }
        const int b = perm[bs];
        out[b * 3 + 0] = fmaxf(r0 + bd[0], 0.f);
        out[b * 3 + 1] = fmaxf(r1 + bd[1], 0.f);
        out[b * 3 + 2] = fmaxf(r2 + bd[2], 0.f);
    }
}

extern "C" void kernel_launch(void* const* d_in, const int* in_sizes, int n_in,
                              void* d_out, int out_size) {
    const float* chars  = (const float*)d_in[0];
    const int*   seqlen = (const int*)  d_in[1];
    const float* W1 = (const float*)d_in[2];
    const float* U1 = (const float*)d_in[3];
    const float* b1 = (const float*)d_in[4];
    const float* W2 = (const float*)d_in[5];
    const float* U2 = (const float*)d_in[6];
    const float* b2 = (const float*)d_in[7];
    const float* Wd = (const float*)d_in[8];
    const float* bd = (const float*)d_in[9];
    float* out = (float*)d_out;

    char *xt, *h1t, *h2t, *w1t, *u1t, *w2t, *u2t;
    float *c1, *c2, *hfin;
    int *perm, *slen, *nact;
    cudaGetSymbolAddress((void**)&xt,   g_xt);
    cudaGetSymbolAddress((void**)&h1t,  g_h1t);
    cudaGetSymbolAddress((void**)&h2t,  g_h2t);
    cudaGetSymbolAddress((void**)&w1t,  g_w1t);
    cudaGetSymbolAddress((void**)&u1t,  g_u1t);
    cudaGetSymbolAddress((void**)&w2t,  g_w2t);
    cudaGetSymbolAddress((void**)&u2t,  g_u2t);
    cudaGetSymbolAddress((void**)&c1,   g_c1);
    cudaGetSymbolAddress((void**)&c2,   g_c2);
    cudaGetSymbolAddress((void**)&hfin, g_hfinal);
    cudaGetSymbolAddress((void**)&perm, g_perm);
    cudaGetSymbolAddress((void**)&slen, g_slen);
    cudaGetSymbolAddress((void**)&nact, g_nact);

    cudaFuncSetAttribute(lstm_step,
                         cudaFuncAttributeMaxDynamicSharedMemorySize, SMEM_BYTES);

    const size_t HSLOT = (size_t)8 * 32 * A_TILE_B;

    // prep (3 launches so ncu -s 5 lands on lstm_step)
    sort_rows<<<1, B_ROWS>>>(seqlen, perm, slen, nact);
    const int nx = B_ROWS * T_STEPS * DIM_IN;
    split_chars_tiled<<<(nx + 255) / 256, 256>>>(chars, perm, xt);
    {
        TransArgs t0 = {W1, w1t, DIM_IN};
        TransArgs t1 = {U1, u1t, HDIM};
        TransArgs t2 = {W2, w2t, HDIM};
        TransArgs t3 = {U2, u2t, HDIM};
        transpose_split_w_all<<<dim3(FOURH / 32, HDIM / 32, 4), dim3(32, 8)>>>(t0, t1, t2, t3);
    }

    auto mkL1 = [&](int t) {
        StepArgs s;
        const int prev = t & 1, cur = (t + 1) & 1;
        s.Ax = xt + (size_t)t * 8 * 8 * A_TILE_B;
        s.Hx = h1t + prev * HSLOT;
        s.Bw = w1t; s.Bu = u1t;
        s.KC0 = DIM_IN / 32;
        s.bias = b1; s.C = c1;
        s.Ot = h1t + cur * HSLOT;
        s.seqlen = nullptr; s.hfinal = nullptr;
        s.nact = nact;
        s.t = t; s.first = (t == 0) ? 1 : 0;
        return s;
    };
    auto mkL2 = [&](int t) {
        StepArgs s;
        const int prev = t & 1, cur = (t + 1) & 1;
        s.Ax = h1t + cur * HSLOT;
        s.Hx = h2t + prev * HSLOT;
        s.Bw = w2t; s.Bu = u2t;
        s.KC0 = HDIM / 32;
        s.bias = b2; s.C = c2;
        s.Ot = h2t + cur * HSLOT;
        s.seqlen = slen; s.hfinal = hfin;
        s.nact = nact;
        s.t = t; s.first = (t == 0) ? 1 : 0;
        return s;
    };

    const dim3 grid1(HDIM / BN, B_ROWS / (2 * BM), 1);   // (32, 4, 1)
    const dim3 grid2(HDIM / BN, B_ROWS / (2 * BM), 2);   // (32, 4, 2) = 256 CTAs

    {
        StepArgs s = mkL1(0);
        lstm_step<<<grid1, NTH, SMEM_BYTES>>>(s, s);
    }
    for (int k = 1; k < T_STEPS; ++k) {
        StepArgs sA = mkL1(k);
        StepArgs sB = mkL2(k - 1);
        lstm_step<<<grid2, NTH, SMEM_BYTES>>>(sA, sB);
    }
    {
        StepArgs s = mkL2(T_STEPS - 1);
        lstm_step<<<grid1, NTH, SMEM_BYTES>>>(s, s);
    }
    dense_kernel<<<B_ROWS, 256>>>(hfin, perm, Wd, bd, out);
}

// round 14
// speedup vs baseline: 1.1424x; 1.1424x over previous
#include <cuda_runtime.h>
#include <cuda_bf16.h>
#include <cstdint>
#include <math.h>

typedef __nv_bfloat16 bf16;

#define B_ROWS   512
#define T_STEPS  128
#define DIM_IN   256
#define HDIM     1024
#define FOURH    4096

#define BM 64
#define BN 32            // columns per gate per block
#define NCONS 256        // 8 consumer warps: 4 (m) x 2 (n)
#define NTH 288          // + 1 producer warp
#define NCTAS 256        // 32 nblk x 8 rowblk — all resident (2/SM x 148 = 296)

// Tile images (gmem layout == smem layout):
#define A_TILE_B  10240
#define B_TILE_B  20480
#define A_PLANE_B 5120
#define B_PLANE_B 10240
#define STAGE_B   (A_TILE_B + B_TILE_B)      // 30720

// smem: [0..24) full mbarriers, [24..48) empty mbarriers, stages at 1024
#define SM_FULL(s)  ((s) * 8)
#define SM_EMPTY(s) (24 + (s) * 8)
#define SM_A_OFF(s) (1024 + (s) * STAGE_B)
#define SM_B_OFF(s) (SM_A_OFF(s) + A_TILE_B)
#define SMEM_BYTES  (1024 + 3 * STAGE_B)     // 93184 -> 2 CTAs/SM

// ---------------- persistent device scratch (sorted row space) ----------------
__device__ __align__(128) char g_xt[(size_t)T_STEPS * 8 * 8 * A_TILE_B];
__device__ __align__(128) char g_h1t[2][(size_t)8 * 32 * A_TILE_B];
__device__ __align__(128) char g_h2t[2][(size_t)8 * 32 * A_TILE_B];
__device__ __align__(128) char g_w1t[(size_t)32 * 8  * B_TILE_B];
__device__ __align__(128) char g_u1t[(size_t)32 * 32 * B_TILE_B];
__device__ __align__(128) char g_w2t[(size_t)32 * 32 * B_TILE_B];
__device__ __align__(128) char g_u2t[(size_t)32 * 32 * B_TILE_B];
__device__ float g_c1[(size_t)B_ROWS * HDIM];
__device__ float g_c2[(size_t)B_ROWS * HDIM];
__device__ float g_hfinal[(size_t)B_ROWS * HDIM];
__device__ int   g_perm[B_ROWS];
__device__ int   g_slen[B_ROWS];
__device__ int   g_nact[T_STEPS];
// global barrier state (count always returns to 0; gen is monotonic -> replay-safe)
__device__ int   g_bar_count;
__device__ int   g_bar_gen;

// ---------------- helpers ----------------
__device__ __forceinline__ uint32_t smem_u32(const void* p) {
    uint32_t a;
    asm("{ .reg .u64 t; cvta.to.shared.u64 t, %1; cvt.u32.u64 %0, t; }" : "=r"(a) : "l"(p));
    return a;
}
__device__ __forceinline__ void mbar_init(uint32_t a, uint32_t cnt) {
    asm volatile("mbarrier.init.shared.b64 [%0], %1;" :: "r"(a), "r"(cnt) : "memory");
}
__device__ __forceinline__ void mbar_expect(uint32_t a, uint32_t bytes) {
    asm volatile("mbarrier.arrive.expect_tx.shared.b64 _, [%0], %1;"
                 :: "r"(a), "r"(bytes) : "memory");
}
__device__ __forceinline__ void mbar_arrive(uint32_t a) {
    asm volatile("mbarrier.arrive.shared.b64 _, [%0];" :: "r"(a) : "memory");
}
__device__ __forceinline__ void mbar_wait(uint32_t a, uint32_t parity) {
    asm volatile(
        "{\n\t.reg .pred P;\n\t"
        "WL_%=:\n\t"
        "mbarrier.try_wait.parity.acquire.cta.shared::cta.b64 P, [%0], %1, 0x989680;\n\t"
        "@P bra.uni WD_%=;\n\t"
        "bra.uni WL_%=;\n\t"
        "WD_%=:\n\t}"
        :: "r"(a), "r"(parity) : "memory");
}
__device__ __forceinline__ void bulk_g2s(uint32_t dst, const void* src,
                                         uint32_t bytes, uint32_t mbar) {
    asm volatile(
        "cp.async.bulk.shared::cluster.global.mbarrier::complete_tx::bytes "
        "[%0], [%1], %2, [%3];"
        :: "r"(dst), "l"(src), "r"(bytes), "r"(mbar) : "memory");
}
__device__ __forceinline__ void ldmx4(uint32_t* r, uint32_t a) {
    asm volatile("ldmatrix.sync.aligned.m8n8.x4.shared.b16 {%0,%1,%2,%3}, [%4];"
                 : "=r"(r[0]), "=r"(r[1]), "=r"(r[2]), "=r"(r[3]) : "r"(a));
}
__device__ __forceinline__ void mma_bf16(float* d, const uint32_t* a, const uint32_t* b) {
    asm volatile(
        "mma.sync.aligned.m16n8k16.row.col.f32.bf16.bf16.f32 "
        "{%0,%1,%2,%3}, {%4,%5,%6,%7}, {%8,%9}, {%0,%1,%2,%3};"
        : "+f"(d[0]), "+f"(d[1]), "+f"(d[2]), "+f"(d[3])
        : "r"(a[0]), "r"(a[1]), "r"(a[2]), "r"(a[3]), "r"(b[0]), "r"(b[1]));
}
__device__ __forceinline__ float fsig(float x) { return 1.0f / (1.0f + __expf(-x)); }
__device__ __forceinline__ void split_bf16(float x, bf16& hi, bf16& lo) {
    hi = __float2bfloat16(x);
    lo = __float2bfloat16(x - __bfloat162float(hi));
}

// ---------------- prep kernels ----------------
__global__ void sort_rows(const int* __restrict__ seqlen,
                          int* __restrict__ perm, int* __restrict__ slen,
                          int* __restrict__ nact) {
    __shared__ int keys[B_ROWS];
    const int i = threadIdx.x;
    keys[i] = seqlen[i];
    __syncthreads();
    const int k = keys[i];
    int rank = 0;
    for (int j = 0; j < B_ROWS; ++j) {
        int kj = keys[j];
        rank += (kj > k) || (kj == k && j < i);
    }
    perm[rank] = i;
    slen[rank] = k;
    if (i < T_STEPS) {
        int cnt = 0;
        for (int j = 0; j < B_ROWS; ++j) cnt += (keys[j] >= i + 1);
        nact[i] = cnt;
    }
}

__global__ void split_chars_tiled(const float* __restrict__ x,
                                  const int* __restrict__ perm,
                                  char* __restrict__ xt) {
    const int n = B_ROWS * T_STEPS * DIM_IN;
    int i = blockIdx.x * blockDim.x + threadIdx.x;
    if (i >= n) return;
    const int row_elems = T_STEPS * DIM_IN;
    int bs = i / row_elems, d = i - bs * row_elems;
    int t = d >> 8, k = d & 255;
    float v = x[(size_t)perm[bs] * row_elems + d];
    bf16 h, l; split_bf16(v, h, l);
    size_t base = (((size_t)t * 8 + (bs >> 6)) * 8 + (k >> 5)) * A_TILE_B
                + (size_t)(bs & 63) * 80 + (k & 31) * 2;
    *reinterpret_cast<bf16*>(xt + base)             = h;
    *reinterpret_cast<bf16*>(xt + base + A_PLANE_B) = l;
}

struct TransArgs { const float* W; char* Wt; int K; };
__global__ void transpose_split_w_all(TransArgs t0, TransArgs t1,
                                      TransArgs t2, TransArgs t3) {
    TransArgs ta = (blockIdx.z == 0) ? t0
                 : (blockIdx.z == 1) ? t1
                 : (blockIdx.z == 2) ? t2 : t3;
    int kb = blockIdx.y * 32;
    if (kb >= ta.K) return;
    __shared__ float tile[32][33];
    int nb = blockIdx.x * 32;
    int x = threadIdx.x, y = threadIdx.y;
    #pragma unroll
    for (int yy = y; yy < 32; yy += 8)
        tile[yy][x] = ta.W[(size_t)(kb + yy) * FOURH + nb + x];
    __syncthreads();
    const int KC = ta.K >> 5;
    #pragma unroll
    for (int yy = y; yy < 32; yy += 8) {
        float w = tile[x][yy];
        bf16 h, l; split_bf16(w, h, l);
        int n4 = nb + yy, k = kb + x;
        int g = n4 >> 10, rr = n4 & 1023;
        int nblk = rr >> 5, nl = rr & 31;
        int kc = k >> 5, kl = k & 31;
        size_t base = ((size_t)(nblk * KC + kc)) * B_TILE_B
                    + (size_t)(g * 32 + nl) * 80 + kl * 2;
        *reinterpret_cast<bf16*>(ta.Wt + base)             = h;
        *reinterpret_cast<bf16*>(ta.Wt + base + B_PLANE_B) = l;
    }
}

// ---------------- persistent fused 2-layer LSTM ----------------
struct PArgs {
    const char* xt;
    char* h1t0; char* h1t1; char* h2t0; char* h2t1;
    const char* w1; const char* u1; const char* w2; const char* u2;
    const float* b1; const float* b2;
    float* c1; float* c2;
    const int* slen; float* hfinal;
    const int* nact;
};

__global__ __launch_bounds__(NTH, 2)
void lstm_persistent(const PArgs P)
{
    extern __shared__ char smemc[];
    const uint32_t sb = smem_u32(smemc);
    const int tid  = threadIdx.x;
    const int lane = tid & 31;
    const int warp = tid >> 5;
    const int nblk = blockIdx.x;
    const int rowblk = blockIdx.y;
    const int row0 = rowblk * BM;
    const int n0   = nblk * BN;
    const size_t HSLOT = (size_t)8 * 32 * A_TILE_B;

    if (tid == 0) {
        #pragma unroll
        for (int s = 0; s < 3; ++s) {
            mbar_init(sb + SM_FULL(s), 1);
            mbar_init(sb + SM_EMPTY(s), 8);
        }
        asm volatile("fence.proxy.async.shared::cta;" ::: "memory");
    }
    __syncthreads();

    // consumer geometry
    const int wm = warp >> 1;
    const int wn = warp & 1;
    const int arow  = (lane & 7) + ((lane >> 3) & 1) * 8;
    const int koffA = (lane >> 4) * 8;
    const int brow4 = (lane & 7) + ((lane >> 4) << 3);
    const int koffB4 = ((lane >> 3) & 1) * 8;

    int iter = 0;   // global chunk counter (identical across all threads of CTA)

    // one job = one (layer, t) GEMM+cell for this CTA's (nblk, rowblk)
    auto do_job = [&](int layer, int t) {
        if (row0 >= P.nact[t]) return;   // dead rows: skip, iter untouched (CTA-local)
        const int first = (t == 0) ? 1 : 0;
        const int KC0i = layer ? 32 : 8;
        const int nch = first ? KC0i : (KC0i + 32);
        const int prev = t & 1, cur = (t + 1) & 1;
        const char* Ax = layer ? ((cur ? P.h1t1 : P.h1t0))
                               : (P.xt + (size_t)t * 8 * 8 * A_TILE_B);
        const char* Hx = layer ? (prev ? P.h2t1 : P.h2t0)
                               : (prev ? P.h1t1 : P.h1t0);
        const char* Bw = layer ? P.w2 : P.w1;
        const char* Bu = layer ? P.u2 : P.u1;
        const float* bias = layer ? P.b2 : P.b1;
        float* C = layer ? P.c2 : P.c1;
        char* Ot = layer ? (cur ? P.h2t1 : P.h2t0)
                         : (cur ? P.h1t1 : P.h1t0);

        if (warp == 8) {
            // ---------------- producer ----------------
            if (lane == 0) {
                for (int c = 0; c < nch; ++c, ++iter) {
                    const int st = iter % 3;
                    if (iter >= 3)
                        mbar_wait(sb + SM_EMPTY(st), (uint32_t)(((iter / 3) - 1) & 1));
                    const int seg = (c < KC0i) ? 0 : 1;
                    const int kc  = seg ? (c - KC0i) : c;
                    const char* As = seg ? (Hx + ((size_t)(rowblk * 32 + kc)) * A_TILE_B)
                                         : (Ax + ((size_t)(rowblk * KC0i + kc)) * A_TILE_B);
                    const char* Bs = seg ? (Bu + ((size_t)(nblk * 32 + kc)) * B_TILE_B)
                                         : (Bw + ((size_t)(nblk * KC0i + kc)) * B_TILE_B);
                    const uint32_t mb = sb + SM_FULL(st);
                    mbar_expect(mb, STAGE_B);
                    bulk_g2s(sb + SM_A_OFF(st), As, A_TILE_B, mb);
                    bulk_g2s(sb + SM_B_OFF(st), Bs, B_TILE_B, mb);
                }
            } else {
                iter += nch;
            }
            return;
        }

        // ---------------- consumer ----------------
        float acc[4][2][4];
        #pragma unroll
        for (int g = 0; g < 4; ++g)
            #pragma unroll
            for (int nt = 0; nt < 2; ++nt)
                #pragma unroll
                for (int q = 0; q < 4; ++q) acc[g][nt][q] = 0.f;

        for (int i = 0; i < nch; ++i, ++iter) {
            const int st = iter % 3;
            mbar_wait(sb + SM_FULL(st), (uint32_t)((iter / 3) & 1));

            const uint32_t aB = sb + SM_A_OFF(st);
            const uint32_t bB = sb + SM_B_OFF(st);

            #pragma unroll
            for (int ks = 0; ks < 2; ++ks) {
                uint32_t ah[4], al[4];
                uint32_t aa = aB + (uint32_t)((wm * 16 + arow) * 80 + (ks * 16 + koffA) * 2);
                ldmx4(ah, aa);
                ldmx4(al, aa + A_PLANE_B);
                #pragma unroll
                for (int g = 0; g < 4; ++g) {
                    uint32_t bh[4], bl[4];
                    uint32_t ba = bB + (uint32_t)((g * 32 + wn * 16 + brow4) * 80
                                                  + (ks * 16 + koffB4) * 2);
                    ldmx4(bh, ba);
                    ldmx4(bl, ba + B_PLANE_B);
                    mma_bf16(acc[g][0], ah, bh);
                    mma_bf16(acc[g][0], ah, bl);
                    mma_bf16(acc[g][0], al, bh);
                    mma_bf16(acc[g][1], ah, bh + 2);
                    mma_bf16(acc[g][1], ah, bl + 2);
                    mma_bf16(acc[g][1], al, bh + 2);
                }
            }
            __syncwarp();
            if (lane == 0) mbar_arrive(sb + SM_EMPTY(st));
        }

        // ---- fused LSTM cell epilogue ----
        #pragma unroll
        for (int half = 0; half < 2; ++half) {
            const int r = row0 + wm * 16 + half * 8 + (lane >> 2);
            const int sl = layer ? P.slen[r] : 0;
            #pragma unroll
            for (int nt = 0; nt < 2; ++nt) {
                const int c = n0 + wn * 16 + nt * 8 + (lane & 3) * 2;
                float2 cold = make_float2(0.f, 0.f);
                if (!first)
                    cold = *reinterpret_cast<const float2*>(C + (size_t)r * HDIM + c);
                float cn[2], hn[2];
                #pragma unroll
                for (int j = 0; j < 2; ++j) {
                    const int q = half * 2 + j;
                    float zi = acc[0][nt][q] + bias[c + j];
                    float zf = acc[1][nt][q] + bias[HDIM + c + j];
                    float zg = acc[2][nt][q] + bias[2 * HDIM + c + j];
                    float zo = acc[3][nt][q] + bias[3 * HDIM + c + j];
                    float ig = fsig(zi), fg = fsig(zf);
                    float gg = tanhf(zg), og = fsig(zo);
                    float co = (j == 0) ? cold.x : cold.y;
                    cn[j] = fmaf(fg, co, ig * gg);
                    hn[j] = og * tanhf(cn[j]);
                }
                *reinterpret_cast<float2*>(C + (size_t)r * HDIM + c) = make_float2(cn[0], cn[1]);
                bf16 h0, l0, h1, l1;
                split_bf16(hn[0], h0, l0);
                split_bf16(hn[1], h1, l1);
                size_t toff = ((size_t)((r >> 6) * 32 + (c >> 5))) * A_TILE_B
                            + (size_t)(r & 63) * 80 + (c & 31) * 2;
                *reinterpret_cast<__nv_bfloat162*>(Ot + toff) = __nv_bfloat162(h0, h1);
                *reinterpret_cast<__nv_bfloat162*>(Ot + toff + A_PLANE_B) =
                    __nv_bfloat162(l0, l1);
                if (layer && sl - 1 == t)
                    *reinterpret_cast<float2*>(P.hfinal + (size_t)r * HDIM + c) =
                        make_float2(hn[0], hn[1]);
            }
        }
    };

    // phase loop: phase ph runs L1(ph) and L2(ph-1); one global barrier per phase.
    for (int ph = 0; ph <= T_STEPS; ++ph) {
        if (ph < T_STEPS) do_job(0, ph);
        if (ph >= 1)      do_job(1, ph - 1);
        if (ph < T_STEPS) {
            __syncthreads();
            if (tid == 0) {
                __threadfence();
                int old_gen = *((volatile int*)&g_bar_gen);
                int prev = atomicAdd(&g_bar_count, 1);
                if (prev == NCTAS - 1) {
                    g_bar_count = 0;
                    __threadfence();
                    atomicAdd(&g_bar_gen, 1);
                } else {
                    while (*((volatile int*)&g_bar_gen) == old_gen) {}
                    __threadfence();
                }
            }
            __syncthreads();
        }
    }
}

// ---------------- final dense(1024->3) + relu (sorted -> original order) ----------------
__global__ void dense_kernel(const float* __restrict__ hfinal,
                             const int* __restrict__ perm,
                             const float* __restrict__ Wd,
                             const float* __restrict__ bd,
                             float* __restrict__ out)
{
    const int bs = blockIdx.x;
    const float* h = hfinal + (size_t)bs * HDIM;

    float s0 = 0.f, s1 = 0.f, s2 = 0.f;
    for (int k = threadIdx.x; k < HDIM; k += blockDim.x) {
        float hv = h[k];
        s0 = fmaf(hv, Wd[k * 3 + 0], s0);
        s1 = fmaf(hv, Wd[k * 3 + 1], s1);
        s2 = fmaf(hv, Wd[k * 3 + 2], s2);
    }
    #pragma unroll
    for (int o = 16; o > 0; o >>= 1) {
        s0 += __shfl_down_sync(0xffffffffu, s0, o);
        s1 += __shfl_down_sync(0xffffffffu, s1, o);
        s2 += __shfl_down_sync(0xffffffffu, s2, o);
    }
    __shared__ float red[8][3];
    const int wid = threadIdx.x >> 5, lane = threadIdx.x & 31;
    if (lane == 0) { red[wid][0] = s0; red[wid][1] = s1; red[wid][2] = s2; }
    __syncthreads();
    if (threadIdx.x == 0) {
        float r0 = 0.f, r1 = 0.f, r2 = 0.f;
        const int nw = blockDim.x >> 5;
        for (int w = 0; w < nw; ++w) { r0 += red[w][0]; r1 += red[w][1]; r2 += red[w][2]; }
        const int b = perm[bs];
        out[b * 3 + 0] = fmaxf(r0 + bd[0], 0.f);
        out[b * 3 + 1] = fmaxf(r1 + bd[1], 0.f);
        out[b * 3 + 2] = fmaxf(r2 + bd[2], 0.f);
    }
}

extern "C" void kernel_launch(void* const* d_in, const int* in_sizes, int n_in,
                              void* d_out, int out_size) {
    const float* chars  = (const float*)d_in[0];
    const int*   seqlen = (const int*)  d_in[1];
    const float* W1 = (const float*)d_in[2];
    const float* U1 = (const float*)d_in[3];
    const float* b1 = (const float*)d_in[4];
    const float* W2 = (const float*)d_in[5];
    const float* U2 = (const float*)d_in[6];
    const float* b2 = (const float*)d_in[7];
    const float* Wd = (const float*)d_in[8];
    const float* bd = (const float*)d_in[9];
    float* out = (float*)d_out;

    char *xt, *h1t, *h2t, *w1t, *u1t, *w2t, *u2t;
    float *c1, *c2, *hfin;
    int *perm, *slen, *nact;
    cudaGetSymbolAddress((void**)&xt,   g_xt);
    cudaGetSymbolAddress((void**)&h1t,  g_h1t);
    cudaGetSymbolAddress((void**)&h2t,  g_h2t);
    cudaGetSymbolAddress((void**)&w1t,  g_w1t);
    cudaGetSymbolAddress((void**)&u1t,  g_u1t);
    cudaGetSymbolAddress((void**)&w2t,  g_w2t);
    cudaGetSymbolAddress((void**)&u2t,  g_u2t);
    cudaGetSymbolAddress((void**)&c1,   g_c1);
    cudaGetSymbolAddress((void**)&c2,   g_c2);
    cudaGetSymbolAddress((void**)&hfin, g_hfinal);
    cudaGetSymbolAddress((void**)&perm, g_perm);
    cudaGetSymbolAddress((void**)&slen, g_slen);
    cudaGetSymbolAddress((void**)&nact, g_nact);

    cudaFuncSetAttribute(lstm_persistent,
                         cudaFuncAttributeMaxDynamicSharedMemorySize, SMEM_BYTES);

    const size_t HSLOT = (size_t)8 * 32 * A_TILE_B;

    // prep
    sort_rows<<<1, B_ROWS>>>(seqlen, perm, slen, nact);
    const int nx = B_ROWS * T_STEPS * DIM_IN;
    split_chars_tiled<<<(nx + 255) / 256, 256>>>(chars, perm, xt);
    {
        TransArgs t0 = {W1, w1t, DIM_IN};
        TransArgs t1 = {U1, u1t, HDIM};
        TransArgs t2 = {W2, w2t, HDIM};
        TransArgs t3 = {U2, u2t, HDIM};
        transpose_split_w_all<<<dim3(FOURH / 32, HDIM / 32, 4), dim3(32, 8)>>>(t0, t1, t2, t3);
    }

    // one persistent kernel for the whole recurrence
    PArgs P;
    P.xt = xt;
    P.h1t0 = h1t;            P.h1t1 = h1t + HSLOT;
    P.h2t0 = h2t;            P.h2t1 = h2t + HSLOT;
    P.w1 = w1t; P.u1 = u1t; P.w2 = w2t; P.u2 = u2t;
    P.b1 = b1;  P.b2 = b2;
    P.c1 = c1;  P.c2 = c2;
    P.slen = slen; P.hfinal = hfin; P.nact = nact;

    lstm_persistent<<<dim3(32, 8, 1), NTH, SMEM_BYTES>>>(P);

    dense_kernel<<<B_ROWS, 256>>>(hfin, perm, Wd, bd, out);
}

// round 15
// speedup vs baseline: 1.3136x; 1.1499x over previous
#include <cuda_runtime.h>
#include <cuda_bf16.h>
#include <cstdint>
#include <math.h>

typedef __nv_bfloat16 bf16;

#define B_ROWS   512
#define T_STEPS  128
#define DIM_IN   256
#define HDIM     1024
#define FOURH    4096

#define BM 64
#define BN 32
#define NTH 288          // 8 consumer warps + 1 producer warp

#define A_TILE_B  10240
#define B_TILE_B  20480
#define A_PLANE_B 5120
#define B_PLANE_B 10240
#define STAGE_B   (A_TILE_B + B_TILE_B)      // 30720

#define SM_FULL(s)  ((s) * 8)
#define SM_EMPTY(s) (24 + (s) * 8)
#define SM_A_OFF(s) (1024 + (s) * STAGE_B)
#define SM_B_OFF(s) (SM_A_OFF(s) + A_TILE_B)
#define SMEM_BYTES  (1024 + 3 * STAGE_B)     // 93184 -> 2 CTAs/SM

// ---------------- persistent device scratch (sorted row space) ----------------
__device__ __align__(128) char g_xt[(size_t)T_STEPS * 8 * 8 * A_TILE_B];
__device__ __align__(128) char g_h1t[2][(size_t)8 * 32 * A_TILE_B];
__device__ __align__(128) char g_h2t[2][(size_t)8 * 32 * A_TILE_B];
__device__ __align__(128) char g_w1t[(size_t)32 * 8  * B_TILE_B];
__device__ __align__(128) char g_u1t[(size_t)32 * 32 * B_TILE_B];
__device__ __align__(128) char g_w2t[(size_t)32 * 32 * B_TILE_B];
__device__ __align__(128) char g_u2t[(size_t)32 * 32 * B_TILE_B];
__device__ float g_c1[(size_t)B_ROWS * HDIM];
__device__ float g_c2[(size_t)B_ROWS * HDIM];
__device__ float g_hfinal[(size_t)B_ROWS * HDIM];
__device__ int   g_perm[B_ROWS];
__device__ int   g_slen[B_ROWS];
__device__ int   g_nact[T_STEPS];
__device__ int   g_cnt[T_STEPS * 8];   // per-(phase, rowblk) arrival counters

// ---------------- helpers ----------------
__device__ __forceinline__ uint32_t smem_u32(const void* p) {
    uint32_t a;
    asm("{ .reg .u64 t; cvta.to.shared.u64 t, %1; cvt.u32.u64 %0, t; }" : "=r"(a) : "l"(p));
    return a;
}
__device__ __forceinline__ void mbar_init(uint32_t a, uint32_t cnt) {
    asm volatile("mbarrier.init.shared.b64 [%0], %1;" :: "r"(a), "r"(cnt) : "memory");
}
__device__ __forceinline__ void mbar_expect(uint32_t a, uint32_t bytes) {
    asm volatile("mbarrier.arrive.expect_tx.shared.b64 _, [%0], %1;"
                 :: "r"(a), "r"(bytes) : "memory");
}
__device__ __forceinline__ void mbar_arrive(uint32_t a) {
    asm volatile("mbarrier.arrive.shared.b64 _, [%0];" :: "r"(a) : "memory");
}
__device__ __forceinline__ void mbar_wait(uint32_t a, uint32_t parity) {
    asm volatile(
        "{\n\t.reg .pred P;\n\t"
        "WL_%=:\n\t"
        "mbarrier.try_wait.parity.acquire.cta.shared::cta.b64 P, [%0], %1, 0x989680;\n\t"
        "@P bra.uni WD_%=;\n\t"
        "bra.uni WL_%=;\n\t"
        "WD_%=:\n\t}"
        :: "r"(a), "r"(parity) : "memory");
}
__device__ __forceinline__ void bulk_g2s(uint32_t dst, const void* src,
                                         uint32_t bytes, uint32_t mbar) {
    asm volatile(
        "cp.async.bulk.shared::cluster.global.mbarrier::complete_tx::bytes "
        "[%0], [%1], %2, [%3];"
        :: "r"(dst), "l"(src), "r"(bytes), "r"(mbar) : "memory");
}
__device__ __forceinline__ void ldmx4(uint32_t* r, uint32_t a) {
    asm volatile("ldmatrix.sync.aligned.m8n8.x4.shared.b16 {%0,%1,%2,%3}, [%4];"
                 : "=r"(r[0]), "=r"(r[1]), "=r"(r[2]), "=r"(r[3]) : "r"(a));
}
__device__ __forceinline__ void mma_bf16(float* d, const uint32_t* a, const uint32_t* b) {
    asm volatile(
        "mma.sync.aligned.m16n8k16.row.col.f32.bf16.bf16.f32 "
        "{%0,%1,%2,%3}, {%4,%5,%6,%7}, {%8,%9}, {%0,%1,%2,%3};"
        : "+f"(d[0]), "+f"(d[1]), "+f"(d[2]), "+f"(d[3])
        : "r"(a[0]), "r"(a[1]), "r"(a[2]), "r"(a[3]), "r"(b[0]), "r"(b[1]));
}
__device__ __forceinline__ float fsig(float x) { return 1.0f / (1.0f + __expf(-x)); }
__device__ __forceinline__ void split_bf16(float x, bf16& hi, bf16& lo) {
    hi = __float2bfloat16(x);
    lo = __float2bfloat16(x - __bfloat162float(hi));
}

// ---------------- prep kernels ----------------
__global__ void sort_rows(const int* __restrict__ seqlen,
                          int* __restrict__ perm, int* __restrict__ slen,
                          int* __restrict__ nact) {
    __shared__ int keys[B_ROWS];
    const int i = threadIdx.x;
    keys[i] = seqlen[i];
    // zero the dataflow counters (per replay)
    for (int z = i; z < T_STEPS * 8; z += B_ROWS) g_cnt[z] = 0;
    __syncthreads();
    const int k = keys[i];
    int rank = 0;
    for (int j = 0; j < B_ROWS; ++j) {
        int kj = keys[j];
        rank += (kj > k) || (kj == k && j < i);
    }
    perm[rank] = i;
    slen[rank] = k;
    if (i < T_STEPS) {
        int cnt = 0;
        for (int j = 0; j < B_ROWS; ++j) cnt += (keys[j] >= i + 1);
        nact[i] = cnt;
    }
}

__global__ void split_chars_tiled(const float* __restrict__ x,
                                  const int* __restrict__ perm,
                                  char* __restrict__ xt) {
    const int n = B_ROWS * T_STEPS * DIM_IN;
    int i = blockIdx.x * blockDim.x + threadIdx.x;
    if (i >= n) return;
    const int row_elems = T_STEPS * DIM_IN;
    int bs = i / row_elems, d = i - bs * row_elems;
    int t = d >> 8, k = d & 255;
    float v = x[(size_t)perm[bs] * row_elems + d];
    bf16 h, l; split_bf16(v, h, l);
    size_t base = (((size_t)t * 8 + (bs >> 6)) * 8 + (k >> 5)) * A_TILE_B
                + (size_t)(bs & 63) * 80 + (k & 31) * 2;
    *reinterpret_cast<bf16*>(xt + base)             = h;
    *reinterpret_cast<bf16*>(xt + base + A_PLANE_B) = l;
}

struct TransArgs { const float* W; char* Wt; int K; };
__global__ void transpose_split_w_all(TransArgs t0, TransArgs t1,
                                      TransArgs t2, TransArgs t3) {
    TransArgs ta = (blockIdx.z == 0) ? t0
                 : (blockIdx.z == 1) ? t1
                 : (blockIdx.z == 2) ? t2 : t3;
    int kb = blockIdx.y * 32;
    if (kb >= ta.K) return;
    __shared__ float tile[32][33];
    int nb = blockIdx.x * 32;
    int x = threadIdx.x, y = threadIdx.y;
    #pragma unroll
    for (int yy = y; yy < 32; yy += 8)
        tile[yy][x] = ta.W[(size_t)(kb + yy) * FOURH + nb + x];
    __syncthreads();
    const int KC = ta.K >> 5;
    #pragma unroll
    for (int yy = y; yy < 32; yy += 8) {
        float w = tile[x][yy];
        bf16 h, l; split_bf16(w, h, l);
        int n4 = nb + yy, k = kb + x;
        int g = n4 >> 10, rr = n4 & 1023;
        int nblk = rr >> 5, nl = rr & 31;
        int kc = k >> 5, kl = k & 31;
        size_t base = ((size_t)(nblk * KC + kc)) * B_TILE_B
                    + (size_t)(g * 32 + nl) * 80 + kl * 2;
        *reinterpret_cast<bf16*>(ta.Wt + base)             = h;
        *reinterpret_cast<bf16*>(ta.Wt + base + B_PLANE_B) = l;
    }
}

// ---------------- persistent fused 2-layer LSTM (per-rowblk dataflow) ----------------
struct PArgs {
    const char* xt;
    char* h1t0; char* h1t1; char* h2t0; char* h2t1;
    const char* w1; const char* u1; const char* w2; const char* u2;
    const float* b1; const float* b2;
    float* c1; float* c2;
    const int* slen; float* hfinal;
    const int* nact;
};

__global__ __launch_bounds__(NTH, 2)
void lstm_persistent(const PArgs P)
{
    extern __shared__ char smemc[];
    const uint32_t sb = smem_u32(smemc);
    const int tid  = threadIdx.x;
    const int lane = tid & 31;
    const int warp = tid >> 5;
    const int nblk = blockIdx.x;
    const int rowblk = blockIdx.y;
    const int row0 = rowblk * BM;
    const int n0   = nblk * BN;

    if (tid == 0) {
        #pragma unroll
        for (int s = 0; s < 3; ++s) {
            mbar_init(sb + SM_FULL(s), 1);
            mbar_init(sb + SM_EMPTY(s), 8);
        }
        asm volatile("fence.proxy.async.shared::cta;" ::: "memory");
    }
    __syncthreads();

    if (warp == 8) {
        // =================== producer warp ===================
        if (lane == 0) {
            int iter = 0;
            for (int ph = 0; ph <= T_STEPS; ++ph) {
                bool waited = (ph == 0);
                auto wait_grp = [&]() {
                    volatile int* p = &g_cnt[(ph - 1) * 8 + rowblk];
                    while (*p < 32) {}
                    __threadfence();
                    waited = true;
                };
                // job 0: L1(ph)
                if (ph < T_STEPS && row0 < P.nact[ph]) {
                    const int t = ph;
                    const int first = (t == 0) ? 1 : 0;
                    const int KC0i = 8;
                    const int nch = first ? 8 : 40;
                    const int prev = t & 1, cur = (t + 1) & 1;
                    const char* Ax = P.xt + (size_t)t * 8 * 8 * A_TILE_B;
                    const char* Hx = prev ? P.h1t1 : P.h1t0;
                    for (int c = 0; c < nch; ++c, ++iter) {
                        if (c == KC0i && !waited) wait_grp();
                        const int st = iter % 3;
                        if (iter >= 3)
                            mbar_wait(sb + SM_EMPTY(st), (uint32_t)(((iter / 3) - 1) & 1));
                        const int seg = (c < KC0i) ? 0 : 1;
                        const int kc  = seg ? (c - KC0i) : c;
                        const char* As = seg ? (Hx + ((size_t)(rowblk * 32 + kc)) * A_TILE_B)
                                             : (Ax + ((size_t)(rowblk * KC0i + kc)) * A_TILE_B);
                        const char* Bs = seg ? (P.u1 + ((size_t)(nblk * 32 + kc)) * B_TILE_B)
                                             : (P.w1 + ((size_t)(nblk * KC0i + kc)) * B_TILE_B);
                        const uint32_t mb = sb + SM_FULL(st);
                        mbar_expect(mb, STAGE_B);
                        bulk_g2s(sb + SM_A_OFF(st), As, A_TILE_B, mb);
                        bulk_g2s(sb + SM_B_OFF(st), Bs, B_TILE_B, mb);
                    }
                }
                // job 1: L2(ph-1)
                if (ph >= 1 && row0 < P.nact[ph - 1]) {
                    if (!waited) wait_grp();
                    const int t = ph - 1;
                    const int first = (t == 0) ? 1 : 0;
                    const int KC0i = 32;
                    const int nch = first ? 32 : 64;
                    const int prev = t & 1, cur = (t + 1) & 1;
                    const char* Ax = cur ? P.h1t1 : P.h1t0;
                    const char* Hx = prev ? P.h2t1 : P.h2t0;
                    for (int c = 0; c < nch; ++c, ++iter) {
                        const int st = iter % 3;
                        if (iter >= 3)
                            mbar_wait(sb + SM_EMPTY(st), (uint32_t)(((iter / 3) - 1) & 1));
                        const int seg = (c < KC0i) ? 0 : 1;
                        const int kc  = seg ? (c - KC0i) : c;
                        const char* As = seg ? (Hx + ((size_t)(rowblk * 32 + kc)) * A_TILE_B)
                                             : (Ax + ((size_t)(rowblk * KC0i + kc)) * A_TILE_B);
                        const char* Bs = seg ? (P.u2 + ((size_t)(nblk * 32 + kc)) * B_TILE_B)
                                             : (P.w2 + ((size_t)(nblk * KC0i + kc)) * B_TILE_B);
                        const uint32_t mb = sb + SM_FULL(st);
                        mbar_expect(mb, STAGE_B);
                        bulk_g2s(sb + SM_A_OFF(st), As, A_TILE_B, mb);
                        bulk_g2s(sb + SM_B_OFF(st), Bs, B_TILE_B, mb);
                    }
                }
            }
        }
        return;
    }

    // =================== consumer warps (0..7) ===================
    const int wm = warp >> 1;
    const int wn = warp & 1;
    const int arow  = (lane & 7) + ((lane >> 3) & 1) * 8;
    const int koffA = (lane >> 4) * 8;
    const int brow4 = (lane & 7) + ((lane >> 4) << 3);
    const int koffB4 = ((lane >> 3) & 1) * 8;

    int iter = 0;

    auto consume_job = [&](int layer, int t) {
        const int first = (t == 0) ? 1 : 0;
        const int KC0i = layer ? 32 : 8;
        const int nch = first ? KC0i : (KC0i + 32);
        const int prev = t & 1, cur = (t + 1) & 1;
        const float* bias = layer ? P.b2 : P.b1;
        float* C = layer ? P.c2 : P.c1;
        char* Ot = layer ? (cur ? P.h2t1 : P.h2t0)
                         : (cur ? P.h1t1 : P.h1t0);

        float acc[4][2][4];
        #pragma unroll
        for (int g = 0; g < 4; ++g)
            #pragma unroll
            for (int nt = 0; nt < 2; ++nt)
                #pragma unroll
                for (int q = 0; q < 4; ++q) acc[g][nt][q] = 0.f;

        for (int i = 0; i < nch; ++i, ++iter) {
            const int st = iter % 3;
            mbar_wait(sb + SM_FULL(st), (uint32_t)((iter / 3) & 1));

            const uint32_t aB = sb + SM_A_OFF(st);
            const uint32_t bB = sb + SM_B_OFF(st);

            #pragma unroll
            for (int ks = 0; ks < 2; ++ks) {
                uint32_t ah[4], al[4];
                uint32_t aa = aB + (uint32_t)((wm * 16 + arow) * 80 + (ks * 16 + koffA) * 2);
                ldmx4(ah, aa);
                ldmx4(al, aa + A_PLANE_B);
                #pragma unroll
                for (int g = 0; g < 4; ++g) {
                    uint32_t bh[4], bl[4];
                    uint32_t ba = bB + (uint32_t)((g * 32 + wn * 16 + brow4) * 80
                                                  + (ks * 16 + koffB4) * 2);
                    ldmx4(bh, ba);
                    ldmx4(bl, ba + B_PLANE_B);
                    mma_bf16(acc[g][0], ah, bh);
                    mma_bf16(acc[g][0], ah, bl);
                    mma_bf16(acc[g][0], al, bh);
                    mma_bf16(acc[g][1], ah, bh + 2);
                    mma_bf16(acc[g][1], ah, bl + 2);
                    mma_bf16(acc[g][1], al, bh + 2);
                }
            }
            __syncwarp();
            if (lane == 0) mbar_arrive(sb + SM_EMPTY(st));
        }

        // ---- fused LSTM cell epilogue ----
        #pragma unroll
        for (int half = 0; half < 2; ++half) {
            const int r = row0 + wm * 16 + half * 8 + (lane >> 2);
            const int sl = layer ? P.slen[r] : 0;
            #pragma unroll
            for (int nt = 0; nt < 2; ++nt) {
                const int c = n0 + wn * 16 + nt * 8 + (lane & 3) * 2;
                float2 cold = make_float2(0.f, 0.f);
                if (!first)
                    cold = *reinterpret_cast<const float2*>(C + (size_t)r * HDIM + c);
                float cn[2], hn[2];
                #pragma unroll
                for (int j = 0; j < 2; ++j) {
                    const int q = half * 2 + j;
                    float zi = acc[0][nt][q] + bias[c + j];
                    float zf = acc[1][nt][q] + bias[HDIM + c + j];
                    float zg = acc[2][nt][q] + bias[2 * HDIM + c + j];
                    float zo = acc[3][nt][q] + bias[3 * HDIM + c + j];
                    float ig = fsig(zi), fg = fsig(zf);
                    float gg = tanhf(zg), og = fsig(zo);
                    float co = (j == 0) ? cold.x : cold.y;
                    cn[j] = fmaf(fg, co, ig * gg);
                    hn[j] = og * tanhf(cn[j]);
                }
                *reinterpret_cast<float2*>(C + (size_t)r * HDIM + c) = make_float2(cn[0], cn[1]);
                bf16 h0, l0, h1, l1;
                split_bf16(hn[0], h0, l0);
                split_bf16(hn[1], h1, l1);
                size_t toff = ((size_t)((r >> 6) * 32 + (c >> 5))) * A_TILE_B
                            + (size_t)(r & 63) * 80 + (c & 31) * 2;
                *reinterpret_cast<__nv_bfloat162*>(Ot + toff) = __nv_bfloat162(h0, h1);
                *reinterpret_cast<__nv_bfloat162*>(Ot + toff + A_PLANE_B) =
                    __nv_bfloat162(l0, l1);
                if (layer && sl - 1 == t)
                    *reinterpret_cast<float2*>(P.hfinal + (size_t)r * HDIM + c) =
                        make_float2(hn[0], hn[1]);
            }
        }
    };

    for (int ph = 0; ph <= T_STEPS; ++ph) {
        if (ph < T_STEPS && row0 < P.nact[ph])   consume_job(0, ph);
        if (ph >= 1 && row0 < P.nact[ph - 1])    consume_job(1, ph - 1);
        if (ph < T_STEPS) {
            // publish this phase's h writes, then single arrival per CTA
            __threadfence();
            asm volatile("bar.sync 1, 256;" ::: "memory");
            if (tid == 0) atomicAdd(&g_cnt[ph * 8 + rowblk], 1);
        }
    }
}

// ---------------- final dense(1024->3) + relu (sorted -> original order) ----------------
__global__ void dense_kernel(const float* __restrict__ hfinal,
                             const int* __restrict__ perm,
                             const float* __restrict__ Wd,
                             const float* __restrict__ bd,
                             float* __restrict__ out)
{
    const int bs = blockIdx.x;
    const float* h = hfinal + (size_t)bs * HDIM;

    float s0 = 0.f, s1 = 0.f, s2 = 0.f;
    for (int k = threadIdx.x; k < HDIM; k += blockDim.x) {
        float hv = h[k];
        s0 = fmaf(hv, Wd[k * 3 + 0], s0);
        s1 = fmaf(hv, Wd[k * 3 + 1], s1);
        s2 = fmaf(hv, Wd[k * 3 + 2], s2);
    }
    #pragma unroll
    for (int o = 16; o > 0; o >>= 1) {
        s0 += __shfl_down_sync(0xffffffffu, s0, o);
        s1 += __shfl_down_sync(0xffffffffu, s1, o);
        s2 += __shfl_down_sync(0xffffffffu, s2, o);
    }
    __shared__ float red[8][3];
    const int wid = threadIdx.x >> 5, lane = threadIdx.x & 31;
    if (lane == 0) { red[wid][0] = s0; red[wid][1] = s1; red[wid][2] = s2; }
    __syncthreads();
    if (threadIdx.x == 0) {
        float r0 = 0.f, r1 = 0.f, r2 = 0.f;
        const int nw = blockDim.x >> 5;
        for (int w = 0; w < nw; ++w) { r0 += red[w][0]; r1 += red[w][1]; r2 += red[w][2]; }
        const int b = perm[bs];
        out[b * 3 + 0] = fmaxf(r0 + bd[0], 0.f);
        out[b * 3 + 1] = fmaxf(r1 + bd[1], 0.f);
        out[b * 3 + 2] = fmaxf(r2 + bd[2], 0.f);
    }
}

extern "C" void kernel_launch(void* const* d_in, const int* in_sizes, int n_in,
                              void* d_out, int out_size) {
    const float* chars  = (const float*)d_in[0];
    const int*   seqlen = (const int*)  d_in[1];
    const float* W1 = (const float*)d_in[2];
    const float* U1 = (const float*)d_in[3];
    const float* b1 = (const float*)d_in[4];
    const float* W2 = (const float*)d_in[5];
    const float* U2 = (const float*)d_in[6];
    const float* b2 = (const float*)d_in[7];
    const float* Wd = (const float*)d_in[8];
    const float* bd = (const float*)d_in[9];
    float* out = (float*)d_out;

    char *xt, *h1t, *h2t, *w1t, *u1t, *w2t, *u2t;
    float *c1, *c2, *hfin;
    int *perm, *slen, *nact;
    cudaGetSymbolAddress((void**)&xt,   g_xt);
    cudaGetSymbolAddress((void**)&h1t,  g_h1t);
    cudaGetSymbolAddress((void**)&h2t,  g_h2t);
    cudaGetSymbolAddress((void**)&w1t,  g_w1t);
    cudaGetSymbolAddress((void**)&u1t,  g_u1t);
    cudaGetSymbolAddress((void**)&w2t,  g_w2t);
    cudaGetSymbolAddress((void**)&u2t,  g_u2t);
    cudaGetSymbolAddress((void**)&c1,   g_c1);
    cudaGetSymbolAddress((void**)&c2,   g_c2);
    cudaGetSymbolAddress((void**)&hfin, g_hfinal);
    cudaGetSymbolAddress((void**)&perm, g_perm);
    cudaGetSymbolAddress((void**)&slen, g_slen);
    cudaGetSymbolAddress((void**)&nact, g_nact);

    cudaFuncSetAttribute(lstm_persistent,
                         cudaFuncAttributeMaxDynamicSharedMemorySize, SMEM_BYTES);

    const size_t HSLOT = (size_t)8 * 32 * A_TILE_B;

    // prep (3 launches; also zeroes dataflow counters each replay)
    sort_rows<<<1, B_ROWS>>>(seqlen, perm, slen, nact);
    const int nx = B_ROWS * T_STEPS * DIM_IN;
    split_chars_tiled<<<(nx + 255) / 256, 256>>>(chars, perm, xt);
    {
        TransArgs t0 = {W1, w1t, DIM_IN};
        TransArgs t1 = {U1, u1t, HDIM};
        TransArgs t2 = {W2, w2t, HDIM};
        TransArgs t3 = {U2, u2t, HDIM};
        transpose_split_w_all<<<dim3(FOURH / 32, HDIM / 32, 4), dim3(32, 8)>>>(t0, t1, t2, t3);
    }

    PArgs P;
    P.xt = xt;
    P.h1t0 = h1t;            P.h1t1 = h1t + HSLOT;
    P.h2t0 = h2t;            P.h2t1 = h2t + HSLOT;
    P.w1 = w1t; P.u1 = u1t; P.w2 = w2t; P.u2 = u2t;
    P.b1 = b1;  P.b2 = b2;
    P.c1 = c1;  P.c2 = c2;
    P.slen = slen; P.hfinal = hfin; P.nact = nact;

    lstm_persistent<<<dim3(32, 8, 1), NTH, SMEM_BYTES>>>(P);

    dense_kernel<<<B_ROWS, 256>>>(hfin, perm, Wd, bd, out);
}

// round 17
// speedup vs baseline: 1.3187x; 1.0038x over previous
#include <cuda_runtime.h>
#include <cuda_bf16.h>
#include <cstdint>
#include <math.h>

typedef __nv_bfloat16 bf16;

#define B_ROWS   512
#define T_STEPS  128
#define DIM_IN   256
#define HDIM     1024
#define FOURH    4096

#define BM 64
#define BN 32
#define NTH 288          // 8 consumer warps + 1 producer warp

#define A_TILE_B  10240
#define B_TILE_B  20480
#define A_PLANE_B 5120
#define B_PLANE_B 10240
#define STAGE_B   (A_TILE_B + B_TILE_B)      // 30720

#define SM_FULL(s)  ((s) * 8)
#define SM_EMPTY(s) (24 + (s) * 8)
#define SM_A_OFF(s) (1024 + (s) * STAGE_B)
#define SM_B_OFF(s) (SM_A_OFF(s) + A_TILE_B)
#define SMEM_BYTES  (1024 + 3 * STAGE_B)     // 93184 -> 2 CTAs/SM

// ---------------- persistent device scratch (sorted row space) ----------------
__device__ __align__(128) char g_xt[(size_t)T_STEPS * 8 * 8 * A_TILE_B];
__device__ __align__(128) char g_h1t[2][(size_t)8 * 32 * A_TILE_B];
__device__ __align__(128) char g_h2t[2][(size_t)8 * 32 * A_TILE_B];
__device__ __align__(128) char g_w1t[(size_t)32 * 8  * B_TILE_B];
__device__ __align__(128) char g_u1t[(size_t)32 * 32 * B_TILE_B];
__device__ __align__(128) char g_w2t[(size_t)32 * 32 * B_TILE_B];
__device__ __align__(128) char g_u2t[(size_t)32 * 32 * B_TILE_B];
__device__ float g_c1[(size_t)B_ROWS * HDIM];
__device__ float g_c2[(size_t)B_ROWS * HDIM];
__device__ float g_hfinal[(size_t)B_ROWS * HDIM];
__device__ int   g_perm[B_ROWS];
__device__ int   g_slen[B_ROWS];
__device__ int   g_nact[T_STEPS];
__device__ int   g_cntL1[T_STEPS * 8];   // published after L1(t) epilogue
__device__ int   g_cntL2[T_STEPS * 8];   // published after L2(t) epilogue

// ---------------- helpers ----------------
__device__ __forceinline__ uint32_t smem_u32(const void* p) {
    uint32_t a;
    asm("{ .reg .u64 t; cvta.to.shared.u64 t, %1; cvt.u32.u64 %0, t; }" : "=r"(a) : "l"(p));
    return a;
}
__device__ __forceinline__ void mbar_init(uint32_t a, uint32_t cnt) {
    asm volatile("mbarrier.init.shared.b64 [%0], %1;" :: "r"(a), "r"(cnt) : "memory");
}
__device__ __forceinline__ void mbar_expect(uint32_t a, uint32_t bytes) {
    asm volatile("mbarrier.arrive.expect_tx.shared.b64 _, [%0], %1;"
                 :: "r"(a), "r"(bytes) : "memory");
}
__device__ __forceinline__ void mbar_arrive(uint32_t a) {
    asm volatile("mbarrier.arrive.shared.b64 _, [%0];" :: "r"(a) : "memory");
}
__device__ __forceinline__ void mbar_wait(uint32_t a, uint32_t parity) {
    asm volatile(
        "{\n\t.reg .pred P;\n\t"
        "WL_%=:\n\t"
        "mbarrier.try_wait.parity.acquire.cta.shared::cta.b64 P, [%0], %1, 0x989680;\n\t"
        "@P bra.uni WD_%=;\n\t"
        "bra.uni WL_%=;\n\t"
        "WD_%=:\n\t}"
        :: "r"(a), "r"(parity) : "memory");
}
__device__ __forceinline__ void bulk_g2s(uint32_t dst, const void* src,
                                         uint32_t bytes, uint32_t mbar) {
    asm volatile(
        "cp.async.bulk.shared::cluster.global.mbarrier::complete_tx::bytes "
        "[%0], [%1], %2, [%3];"
        :: "r"(dst), "l"(src), "r"(bytes), "r"(mbar) : "memory");
}
__device__ __forceinline__ void ldmx4(uint32_t* r, uint32_t a) {
    asm volatile("ldmatrix.sync.aligned.m8n8.x4.shared.b16 {%0,%1,%2,%3}, [%4];"
                 : "=r"(r[0]), "=r"(r[1]), "=r"(r[2]), "=r"(r[3]) : "r"(a));
}
__device__ __forceinline__ void mma_bf16(float* d, const uint32_t* a, const uint32_t* b) {
    asm volatile(
        "mma.sync.aligned.m16n8k16.row.col.f32.bf16.bf16.f32 "
        "{%0,%1,%2,%3}, {%4,%5,%6,%7}, {%8,%9}, {%0,%1,%2,%3};"
        : "+f"(d[0]), "+f"(d[1]), "+f"(d[2]), "+f"(d[3])
        : "r"(a[0]), "r"(a[1]), "r"(a[2]), "r"(a[3]), "r"(b[0]), "r"(b[1]));
}
__device__ __forceinline__ float fsig(float x) { return 1.0f / (1.0f + __expf(-x)); }
__device__ __forceinline__ void split_bf16(float x, bf16& hi, bf16& lo) {
    hi = __float2bfloat16(x);
    lo = __float2bfloat16(x - __bfloat162float(hi));
}

// ---------------- prep kernels ----------------
__global__ void sort_rows(const int* __restrict__ seqlen,
                          int* __restrict__ perm, int* __restrict__ slen,
                          int* __restrict__ nact) {
    __shared__ int keys[B_ROWS];
    const int i = threadIdx.x;
    keys[i] = seqlen[i];
    for (int z = i; z < T_STEPS * 8; z += B_ROWS) { g_cntL1[z] = 0; g_cntL2[z] = 0; }
    __syncthreads();
    const int k = keys[i];
    int rank = 0;
    for (int j = 0; j < B_ROWS; ++j) {
        int kj = keys[j];
        rank += (kj > k) || (kj == k && j < i);
    }
    perm[rank] = i;
    slen[rank] = k;
    if (i < T_STEPS) {
        int cnt = 0;
        for (int j = 0; j < B_ROWS; ++j) cnt += (keys[j] >= i + 1);
        nact[i] = cnt;
    }
}

__global__ void split_chars_tiled(const float* __restrict__ x,
                                  const int* __restrict__ perm,
                                  char* __restrict__ xt) {
    const int n = B_ROWS * T_STEPS * DIM_IN;
    int i = blockIdx.x * blockDim.x + threadIdx.x;
    if (i >= n) return;
    const int row_elems = T_STEPS * DIM_IN;
    int bs = i / row_elems, d = i - bs * row_elems;
    int t = d >> 8, k = d & 255;
    float v = x[(size_t)perm[bs] * row_elems + d];
    bf16 h, l; split_bf16(v, h, l);
    size_t base = (((size_t)t * 8 + (bs >> 6)) * 8 + (k >> 5)) * A_TILE_B
                + (size_t)(bs & 63) * 80 + (k & 31) * 2;
    *reinterpret_cast<bf16*>(xt + base)             = h;
    *reinterpret_cast<bf16*>(xt + base + A_PLANE_B) = l;
}

struct TransArgs { const float* W; char* Wt; int K; };
__global__ void transpose_split_w_all(TransArgs t0, TransArgs t1,
                                      TransArgs t2, TransArgs t3) {
    TransArgs ta = (blockIdx.z == 0) ? t0
                 : (blockIdx.z == 1) ? t1
                 : (blockIdx.z == 2) ? t2 : t3;
    int kb = blockIdx.y * 32;
    if (kb >= ta.K) return;
    __shared__ float tile[32][33];
    int nb = blockIdx.x * 32;
    int x = threadIdx.x, y = threadIdx.y;
    #pragma unroll
    for (int yy = y; yy < 32; yy += 8)
        tile[yy][x] = ta.W[(size_t)(kb + yy) * FOURH + nb + x];
    __syncthreads();
    const int KC = ta.K >> 5;
    #pragma unroll
    for (int yy = y; yy < 32; yy += 8) {
        float w = tile[x][yy];
        bf16 h, l; split_bf16(w, h, l);
        int n4 = nb + yy, k = kb + x;
        int g = n4 >> 10, rr = n4 & 1023;
        int nblk = rr >> 5, nl = rr & 31;
        int kc = k >> 5, kl = k & 31;
        size_t base = ((size_t)(nblk * KC + kc)) * B_TILE_B
                    + (size_t)(g * 32 + nl) * 80 + kl * 2;
        *reinterpret_cast<bf16*>(ta.Wt + base)             = h;
        *reinterpret_cast<bf16*>(ta.Wt + base + B_PLANE_B) = l;
    }
}

// ---------------- persistent fused 2-layer LSTM (split dataflow counters) -------
struct PArgs {
    const char* xt;
    char* h1t0; char* h1t1; char* h2t0; char* h2t1;
    const char* w1; const char* u1; const char* w2; const char* u2;
    const float* b1; const float* b2;
    float* c1; float* c2;
    const int* slen; float* hfinal;
    const int* nact;
};

__global__ __launch_bounds__(NTH, 2)
void lstm_persistent(const PArgs P)
{
    extern __shared__ char smemc[];
    const uint32_t sb = smem_u32(smemc);
    const int tid  = threadIdx.x;
    const int lane = tid & 31;
    const int warp = tid >> 5;
    const int nblk = blockIdx.x;
    const int rowblk = blockIdx.y;
    const int row0 = rowblk * BM;
    const int n0   = nblk * BN;

    if (tid == 0) {
        #pragma unroll
        for (int s = 0; s < 3; ++s) {
            mbar_init(sb + SM_FULL(s), 1);
            mbar_init(sb + SM_EMPTY(s), 8);
        }
        asm volatile("fence.proxy.async.shared::cta;" ::: "memory");
    }
    __syncthreads();

    if (warp == 8) {
        // =================== producer warp ===================
        if (lane == 0) {
            int iter = 0;
            auto wait_cnt = [&](volatile int* p) {
                while (*p < 32) {}
                __threadfence();
            };
            for (int ph = 0; ph <= T_STEPS; ++ph) {
                // -------- job 0: L1(ph) --------
                if (ph < T_STEPS && row0 < P.nact[ph]) {
                    const int t = ph;
                    const int first = (t == 0) ? 1 : 0;
                    const int nch = first ? 8 : 40;
                    const int prev = t & 1;
                    const char* Ax = P.xt + (size_t)t * 8 * 8 * A_TILE_B;
                    const char* Hx = prev ? P.h1t1 : P.h1t0;
                    for (int c = 0; c < nch; ++c, ++iter) {
                        if (c == 8)   // first h1-dependent chunk
                            wait_cnt(&g_cntL1[(ph - 1) * 8 + rowblk]);
                        const int st = iter % 3;
                        if (iter >= 3)
                            mbar_wait(sb + SM_EMPTY(st), (uint32_t)(((iter / 3) - 1) & 1));
                        const int seg = (c < 8) ? 0 : 1;
                        const int kc  = seg ? (c - 8) : c;
                        const char* As = seg ? (Hx + ((size_t)(rowblk * 32 + kc)) * A_TILE_B)
                                             : (Ax + ((size_t)(rowblk * 8 + kc)) * A_TILE_B);
                        const char* Bs = seg ? (P.u1 + ((size_t)(nblk * 32 + kc)) * B_TILE_B)
                                             : (P.w1 + ((size_t)(nblk * 8 + kc)) * B_TILE_B);
                        const uint32_t mb = sb + SM_FULL(st);
                        mbar_expect(mb, STAGE_B);
                        bulk_g2s(sb + SM_A_OFF(st), As, A_TILE_B, mb);
                        bulk_g2s(sb + SM_B_OFF(st), Bs, B_TILE_B, mb);
                    }
                }
                // -------- job 1: L2(ph-1) --------
                if (ph >= 1 && row0 < P.nact[ph - 1]) {
                    const int t = ph - 1;
                    const int first = (t == 0) ? 1 : 0;
                    const int nch = first ? 32 : 64;
                    const int prev = t & 1, cur = (t + 1) & 1;
                    const char* Ax = cur ? P.h1t1 : P.h1t0;   // h1 output of L1(t)
                    const char* Hx = prev ? P.h2t1 : P.h2t0;  // h2 output of L2(t-1)
                    wait_cnt(&g_cntL1[t * 8 + rowblk]);       // gate A (h1(t))
                    for (int c = 0; c < nch; ++c, ++iter) {
                        if (c == 32)  // first h2-dependent chunk
                            wait_cnt(&g_cntL2[(t - 1) * 8 + rowblk]);
                        const int st = iter % 3;
                        if (iter >= 3)
                            mbar_wait(sb + SM_EMPTY(st), (uint32_t)(((iter / 3) - 1) & 1));
                        const int seg = (c < 32) ? 0 : 1;
                        const int kc  = seg ? (c - 32) : c;
                        const char* As = seg ? (Hx + ((size_t)(rowblk * 32 + kc)) * A_TILE_B)
                                             : (Ax + ((size_t)(rowblk * 32 + kc)) * A_TILE_B);
                        const char* Bs = seg ? (P.u2 + ((size_t)(nblk * 32 + kc)) * B_TILE_B)
                                             : (P.w2 + ((size_t)(nblk * 32 + kc)) * B_TILE_B);
                        const uint32_t mb = sb + SM_FULL(st);
                        mbar_expect(mb, STAGE_B);
                        bulk_g2s(sb + SM_A_OFF(st), As, A_TILE_B, mb);
                        bulk_g2s(sb + SM_B_OFF(st), Bs, B_TILE_B, mb);
                    }
                }
            }
        }
        return;
    }

    // =================== consumer warps (0..7) ===================
    const int wm = warp >> 1;
    const int wn = warp & 1;
    const int arow  = (lane & 7) + ((lane >> 3) & 1) * 8;
    const int koffA = (lane >> 4) * 8;
    const int brow4 = (lane & 7) + ((lane >> 4) << 3);
    const int koffB4 = ((lane >> 3) & 1) * 8;

    int iter = 0;

    auto consume_job = [&](int layer, int t) {
        const int first = (t == 0) ? 1 : 0;
        const int KC0i = layer ? 32 : 8;
        const int nch = first ? KC0i : (KC0i + 32);
        const int cur = (t + 1) & 1;
        const float* bias = layer ? P.b2 : P.b1;
        float* C = layer ? P.c2 : P.c1;
        char* Ot = layer ? (cur ? P.h2t1 : P.h2t0)
                         : (cur ? P.h1t1 : P.h1t0);

        float acc[4][2][4];
        #pragma unroll
        for (int g = 0; g < 4; ++g)
            #pragma unroll
            for (int nt = 0; nt < 2; ++nt)
                #pragma unroll
                for (int q = 0; q < 4; ++q) acc[g][nt][q] = 0.f;

        for (int i = 0; i < nch; ++i, ++iter) {
            const int st = iter % 3;
            mbar_wait(sb + SM_FULL(st), (uint32_t)((iter / 3) & 1));

            const uint32_t aB = sb + SM_A_OFF(st);
            const uint32_t bB = sb + SM_B_OFF(st);

            #pragma unroll
            for (int ks = 0; ks < 2; ++ks) {
                uint32_t ah[4], al[4];
                uint32_t aa = aB + (uint32_t)((wm * 16 + arow) * 80 + (ks * 16 + koffA) * 2);
                ldmx4(ah, aa);
                ldmx4(al, aa + A_PLANE_B);
                #pragma unroll
                for (int g = 0; g < 4; ++g) {
                    uint32_t bh[4], bl[4];
                    uint32_t ba = bB + (uint32_t)((g * 32 + wn * 16 + brow4) * 80
                                                  + (ks * 16 + koffB4) * 2);
                    ldmx4(bh, ba);
                    ldmx4(bl, ba + B_PLANE_B);
                    mma_bf16(acc[g][0], ah, bh);
                    mma_bf16(acc[g][0], ah, bl);
                    mma_bf16(acc[g][0], al, bh);
                    mma_bf16(acc[g][1], ah, bh + 2);
                    mma_bf16(acc[g][1], ah, bl + 2);
                    mma_bf16(acc[g][1], al, bh + 2);
                }
            }
            __syncwarp();
            if (lane == 0) mbar_arrive(sb + SM_EMPTY(st));
        }

        // WAR gate: L1(t) overwrites h1 slot whose last reader is L2(t-2).
        // Wait until all 32 CTAs of this rowblk group finished consuming L2(t-2).
        if (layer == 0 && t >= 2) {
            if (tid == 0) {
                volatile int* p = &g_cntL2[(t - 2) * 8 + rowblk];
                while (*p < 32) {}
                __threadfence();
            }
            asm volatile("bar.sync 2, 256;" ::: "memory");
        }

        // ---- fused LSTM cell epilogue ----
        #pragma unroll
        for (int half = 0; half < 2; ++half) {
            const int r = row0 + wm * 16 + half * 8 + (lane >> 2);
            const int sl = layer ? P.slen[r] : 0;
            #pragma unroll
            for (int nt = 0; nt < 2; ++nt) {
                const int c = n0 + wn * 16 + nt * 8 + (lane & 3) * 2;
                float2 cold = make_float2(0.f, 0.f);
                if (!first)
                    cold = *reinterpret_cast<const float2*>(C + (size_t)r * HDIM + c);
                float cn[2], hn[2];
                #pragma unroll
                for (int j = 0; j < 2; ++j) {
                    const int q = half * 2 + j;
                    float zi = acc[0][nt][q] + bias[c + j];
                    float zf = acc[1][nt][q] + bias[HDIM + c + j];
                    float zg = acc[2][nt][q] + bias[2 * HDIM + c + j];
                    float zo = acc[3][nt][q] + bias[3 * HDIM + c + j];
                    float ig = fsig(zi), fg = fsig(zf);
                    float gg = tanhf(zg), og = fsig(zo);
                    float co = (j == 0) ? cold.x : cold.y;
                    cn[j] = fmaf(fg, co, ig * gg);
                    hn[j] = og * tanhf(cn[j]);
                }
                *reinterpret_cast<float2*>(C + (size_t)r * HDIM + c) = make_float2(cn[0], cn[1]);
                bf16 h0, l0, h1, l1;
                split_bf16(hn[0], h0, l0);
                split_bf16(hn[1], h1, l1);
                size_t toff = ((size_t)((r >> 6) * 32 + (c >> 5))) * A_TILE_B
                            + (size_t)(r & 63) * 80 + (c & 31) * 2;
                *reinterpret_cast<__nv_bfloat162*>(Ot + toff) = __nv_bfloat162(h0, h1);
                *reinterpret_cast<__nv_bfloat162*>(Ot + toff + A_PLANE_B) =
                    __nv_bfloat162(l0, l1);
                if (layer && sl - 1 == t)
                    *reinterpret_cast<float2*>(P.hfinal + (size_t)r * HDIM + c) =
                        make_float2(hn[0], hn[1]);
            }
        }
    };

    for (int ph = 0; ph <= T_STEPS; ++ph) {
        // L1(ph), then publish cntL1[ph] immediately (unblocks next phase's producers)
        if (ph < T_STEPS) {
            if (row0 < P.nact[ph]) consume_job(0, ph);
            __threadfence();
            asm volatile("bar.sync 1, 256;" ::: "memory");
            if (tid == 0) atomicAdd(&g_cntL1[ph * 8 + rowblk], 1);
        }
        // L2(ph-1), then publish cntL2[ph-1]
        if (ph >= 1) {
            if (row0 < P.nact[ph - 1]) consume_job(1, ph - 1);
            __threadfence();
            asm volatile("bar.sync 1, 256;" ::: "memory");
            if (tid == 0) atomicAdd(&g_cntL2[(ph - 1) * 8 + rowblk], 1);
        }
    }
}

// ---------------- final dense(1024->3) + relu (sorted -> original order) ----------------
__global__ void dense_kernel(const float* __restrict__ hfinal,
                             const int* __restrict__ perm,
                             const float* __restrict__ Wd,
                             const float* __restrict__ bd,
                             float* __restrict__ out)
{
    const int bs = blockIdx.x;
    const float* h = hfinal + (size_t)bs * HDIM;

    float s0 = 0.f, s1 = 0.f, s2 = 0.f;
    for (int k = threadIdx.x; k < HDIM; k += blockDim.x) {
        float hv = h[k];
        s0 = fmaf(hv, Wd[k * 3 + 0], s0);
        s1 = fmaf(hv, Wd[k * 3 + 1], s1);
        s2 = fmaf(hv, Wd[k * 3 + 2], s2);
    }
    #pragma unroll
    for (int o = 16; o > 0; o >>= 1) {
        s0 += __shfl_down_sync(0xffffffffu, s0, o);
        s1 += __shfl_down_sync(0xffffffffu, s1, o);
        s2 += __shfl_down_sync(0xffffffffu, s2, o);
    }
    __shared__ float red[8][3];
    const int wid = threadIdx.x >> 5, lane = threadIdx.x & 31;
    if (lane == 0) { red[wid][0] = s0; red[wid][1] = s1; red[wid][2] = s2; }
    __syncthreads();
    if (threadIdx.x == 0) {
        float r0 = 0.f, r1 = 0.f, r2 = 0.f;
        const int nw = blockDim.x >> 5;
        for (int w = 0; w < nw; ++w) { r0 += red[w][0]; r1 += red[w][1]; r2 += red[w][2]; }
        const int b = perm[bs];
        out[b * 3 + 0] = fmaxf(r0 + bd[0], 0.f);
        out[b * 3 + 1] = fmaxf(r1 + bd[1], 0.f);
        out[b * 3 + 2] = fmaxf(r2 + bd[2], 0.f);
    }
}

extern "C" void kernel_launch(void* const* d_in, const int* in_sizes, int n_in,
                              void* d_out, int out_size) {
    const float* chars  = (const float*)d_in[0];
    const int*   seqlen = (const int*)  d_in[1];
    const float* W1 = (const float*)d_in[2];
    const float* U1 = (const float*)d_in[3];
    const float* b1 = (const float*)d_in[4];
    const float* W2 = (const float*)d_in[5];
    const float* U2 = (const float*)d_in[6];
    const float* b2 = (const float*)d_in[7];
    const float* Wd = (const float*)d_in[8];
    const float* bd = (const float*)d_in[9];
    float* out = (float*)d_out;

    char *xt, *h1t, *h2t, *w1t, *u1t, *w2t, *u2t;
    float *c1, *c2, *hfin;
    int *perm, *slen, *nact;
    cudaGetSymbolAddress((void**)&xt,   g_xt);
    cudaGetSymbolAddress((void**)&h1t,  g_h1t);
    cudaGetSymbolAddress((void**)&h2t,  g_h2t);
    cudaGetSymbolAddress((void**)&w1t,  g_w1t);
    cudaGetSymbolAddress((void**)&u1t,  g_u1t);
    cudaGetSymbolAddress((void**)&w2t,  g_w2t);
    cudaGetSymbolAddress((void**)&u2t,  g_u2t);
    cudaGetSymbolAddress((void**)&c1,   g_c1);
    cudaGetSymbolAddress((void**)&c2,   g_c2);
    cudaGetSymbolAddress((void**)&hfin, g_hfinal);
    cudaGetSymbolAddress((void**)&perm, g_perm);
    cudaGetSymbolAddress((void**)&slen, g_slen);
    cudaGetSymbolAddress((void**)&nact, g_nact);

    cudaFuncSetAttribute(lstm_persistent,
                         cudaFuncAttributeMaxDynamicSharedMemorySize, SMEM_BYTES);

    const size_t HSLOT = (size_t)8 * 32 * A_TILE_B;

    // prep (3 launches; also zeroes dataflow counters each replay)
    sort_rows<<<1, B_ROWS>>>(seqlen, perm, slen, nact);
    const int nx = B_ROWS * T_STEPS * DIM_IN;
    split_chars_tiled<<<(nx + 255) / 256, 256>>>(chars, perm, xt);
    {
        TransArgs t0 = {W1, w1t, DIM_IN};
        TransArgs t1 = {U1, u1t, HDIM};
        TransArgs t2 = {W2, w2t, HDIM};
        TransArgs t3 = {U2, u2t, HDIM};
        transpose_split_w_all<<<dim3(FOURH / 32, HDIM / 32, 4), dim3(32, 8)>>>(t0, t1, t2, t3);
    }

    PArgs P;
    P.xt = xt;
    P.h1t0 = h1t;            P.h1t1 = h1t + HSLOT;
    P.h2t0 = h2t;            P.h2t1 = h2t + HSLOT;
    P.w1 = w1t; P.u1 = u1t; P.w2 = w2t; P.u2 = u2t;
    P.b1 = b1;  P.b2 = b2;
    P.c1 = c1;  P.c2 = c2;
    P.slen = slen; P.hfinal = hfin; P.nact = nact;

    lstm_persistent<<<dim3(32, 8, 1), NTH, SMEM_BYTES>>>(P);

    dense_kernel<<<B_ROWS, 256>>>(hfin, perm, Wd, bd, out);
}